// round 6
// baseline (speedup 1.0000x reference)
#include <cuda_runtime.h>
#include <cstdint>

// x:[4096,4096] f32, qweight:[4096,1376] i32 (8x int4 along O), scales:[32,11008] f32,
// qzeros:[32,1376] i32, out:[4096,11008] f32, group_size=128.
// tf32 mma.sync GEMM. A (x) pre-rounded to tf32 in a device scratch, then cp.async'd
// into swizzled SMEM. B (W) dequantized in registers and stored to SMEM.

#define I_DIM 4096
#define O_DIM 11008
#define OPACK 1376
#define BM 128
#define BN 256
#define BK 32
#define NITER 128
#define THREADS 512

#define A_WORDS (BM * BK)                 // 4096
#define B_WORDS (BN * BK)                 // 8192
#define STAGE_WORDS (A_WORDS + B_WORDS)   // 12288
#define SMEM_BYTES (2 * STAGE_WORDS * 4)  // 98304

__device__ float g_xr[(size_t)I_DIM * 4096];   // tf32-rounded x

__device__ __forceinline__ uint32_t f2tf32(float f) {
    uint32_t u;
    asm("cvt.rna.tf32.f32 %0, %1;" : "=r"(u) : "f"(f));
    return u;
}

__device__ __forceinline__ uint32_t smem_u32(const void* p) {
    uint32_t a;
    asm("{ .reg .u64 t; cvta.to.shared.u64 t, %1; cvt.u32.u64 %0, t; }" : "=r"(a) : "l"(p));
    return a;
}

__device__ __forceinline__ void cp_async16(uint32_t dst, const void* src) {
    asm volatile("cp.async.cg.shared.global [%0], [%1], 16;" :: "r"(dst), "l"(src) : "memory");
}

__device__ __forceinline__ void mma_tf32(float* d, const uint32_t* a, const uint32_t* b) {
    asm volatile(
        "mma.sync.aligned.m16n8k8.row.col.f32.tf32.tf32.f32 "
        "{%0,%1,%2,%3},{%4,%5,%6,%7},{%8,%9},{%0,%1,%2,%3};"
        : "+f"(d[0]), "+f"(d[1]), "+f"(d[2]), "+f"(d[3])
        : "r"(a[0]), "r"(a[1]), "r"(a[2]), "r"(a[3]), "r"(b[0]), "r"(b[1]));
}

// ---------------- pre-kernel: round x to tf32 (exact rna, idempotent) ----------------
__global__ __launch_bounds__(256)
void round_x_kernel(const float4* __restrict__ x) {
    size_t i = (size_t)blockIdx.x * 256 + threadIdx.x;   // over float4 elements
    float4 v = x[i];
    uint4 u;
    u.x = f2tf32(v.x); u.y = f2tf32(v.y); u.z = f2tf32(v.z); u.w = f2tf32(v.w);
    reinterpret_cast<uint4*>(g_xr)[i] = u;
}

// ---------------- main GEMM ----------------
__global__ __launch_bounds__(THREADS, 1)
void q4_tf32_mma(const int* __restrict__ qweight,
                 const float* __restrict__ scales,
                 const int* __restrict__ qzeros,
                 float* __restrict__ out) {
    extern __shared__ uint32_t smem[];
    const uint32_t sbase = smem_u32(smem);

    const int tid  = threadIdx.x;
    const int lane = tid & 31;
    const int wid  = tid >> 5;
    const int gi   = lane >> 2;   // 0..7
    const int tq   = lane & 3;    // 0..3

    const int row0 = blockIdx.y * BM;
    const int col0 = blockIdx.x * BN;

    // 16 warps: 2 (M, tile 64) x 8 (N, tile 32)
    const int wm = wid & 1;
    const int wn = wid >> 1;

    // B loader: ow = qweight word column (0..31), kt = k-pair index (0..15)
    const int ow = tid & 31;
    const int kt = tid >> 5;
    const int*   qw_base = qweight + (col0 >> 3) + ow;
    const int*   qz_base = qzeros  + (col0 >> 3) + ow;
    const float* sc_base = scales  + col0 + ow * 8;

    uint32_t wS0, wS1, zS;
    float4 sS0, sS1;

    float acc[4][4][4];
#pragma unroll
    for (int mi = 0; mi < 4; mi++)
#pragma unroll
        for (int nb = 0; nb < 4; nb++)
#pragma unroll
            for (int j = 0; j < 4; j++) acc[mi][nb][j] = 0.0f;

    // ---- A: issue cp.async of x tile (pre-rounded) into swizzled SMEM ----
    auto issueA = [&](int it, int stage) {
        const int k0 = it * BK;
        const uint32_t aB = sbase + stage * (STAGE_WORDS * 4);
#pragma unroll
        for (int j = 0; j < 2; j++) {
            int c = tid + j * 512;          // 0..1023 16B-chunks
            int ar = c >> 3;                // row 0..127
            int af4 = c & 7;                // 16B chunk within 128B row
            const float* src = g_xr + (size_t)(row0 + ar) * I_DIM + k0 + af4 * 4;
            uint32_t w = ar * 32 + ((af4 ^ (ar & 7)) << 2);
            cp_async16(aB + w * 4, src);
        }
        asm volatile("cp.async.commit_group;" ::: "memory");
    };

    // ---- B: gmem -> regs ----
    auto loadB = [&](int it) {
        const int k0 = it * BK;
        wS0 = (uint32_t)qw_base[(size_t)(k0 + 2 * kt) * OPACK];
        wS1 = (uint32_t)qw_base[(size_t)(k0 + 2 * kt + 1) * OPACK];
        const int g = it >> 2;
        zS  = (uint32_t)qz_base[(size_t)g * OPACK];
        sS0 = *reinterpret_cast<const float4*>(sc_base + (size_t)g * O_DIM);
        sS1 = *reinterpret_cast<const float4*>(sc_base + (size_t)g * O_DIM + 4);
    };

    // ---- B: dequant regs -> swizzled SMEM ----
    // word(n,k) = n*32 + (((k>>2) ^ (n&7) ^ ((n>>3)&7)) << 2) + (k&3)
    auto storeB = [&](int stage) {
        uint32_t* Bs = smem + stage * STAGE_WORDS + A_WORDS;
        const int kq2 = kt >> 1;        // k>>2
        const int klo = (kt & 1) * 2;   // k&3 (pair base)
        float sc[8] = {sS0.x, sS0.y, sS0.z, sS0.w, sS1.x, sS1.y, sS1.z, sS1.w};
#pragma unroll
        for (int o = 0; o < 8; o++) {
            float fz = __uint_as_float(0x4B000000u | ((zS >> (4 * o)) & 0xF));
            float f0 = __uint_as_float(0x4B000000u | ((wS0 >> (4 * o)) & 0xF));
            float f1 = __uint_as_float(0x4B000000u | ((wS1 >> (4 * o)) & 0xF));
            uint2 v;
            v.x = f2tf32((f0 - fz) * sc[o]);   // exact integer diff, then scale
            v.y = f2tf32((f1 - fz) * sc[o]);
            int n = ow * 8 + o;
            uint32_t w = n * 32 + ((kq2 ^ o ^ (ow & 7)) << 2) + klo;
            *reinterpret_cast<uint2*>(Bs + w) = v;
        }
    };

    auto compute = [&](int stage) {
        const uint32_t* As = smem + stage * STAGE_WORDS;
        const uint32_t* Bs = As + A_WORDS;
#pragma unroll
        for (int kb = 0; kb < 4; kb++) {
            uint32_t a[4][4];
#pragma unroll
            for (int mi = 0; mi < 4; mi++) {
                uint32_t base = (wm * 64 + mi * 16 + gi) * 32 + (((2 * kb) ^ gi) << 2) + tq;
                a[mi][0] = As[base];
                a[mi][1] = As[base + 256];     // row +8
                a[mi][2] = As[base ^ 4];       // k +4
                a[mi][3] = As[(base ^ 4) + 256];
            }
            uint32_t b[4][2];
#pragma unroll
            for (int nb = 0; nb < 4; nb++) {
                int n = wn * 32 + nb * 8 + gi;
                int d = (wn * 4 + nb) & 7;     // (n>>3)&7
                uint32_t base = n * 32 + (((2 * kb) ^ gi ^ d) << 2) + tq;
                b[nb][0] = Bs[base];
                b[nb][1] = Bs[base ^ 4];
            }
#pragma unroll
            for (int mi = 0; mi < 4; mi++)
#pragma unroll
                for (int nb = 0; nb < 4; nb++)
                    mma_tf32(acc[mi][nb], a[mi], b[nb]);
        }
    };

    // ---------------- pipeline ----------------
    issueA(0, 0);
    loadB(0);
    asm volatile("cp.async.wait_group 0;" ::: "memory");
    storeB(0);
    __syncthreads();

    for (int it = 0; it < NITER; ++it) {
        const int s = it & 1;
        if (it + 1 < NITER) {
            issueA(it + 1, s ^ 1);
            loadB(it + 1);
        }
        compute(s);
        if (it + 1 < NITER) {
            asm volatile("cp.async.wait_group 0;" ::: "memory");
            storeB(s ^ 1);
        }
        __syncthreads();
    }

    // ---------------- epilogue ----------------
#pragma unroll
    for (int mi = 0; mi < 4; mi++) {
        int r = row0 + wm * 64 + mi * 16 + gi;
        float* o0 = out + (size_t)r * O_DIM + col0 + wn * 32;
        float* o1 = o0 + 8 * O_DIM;
#pragma unroll
        for (int nb = 0; nb < 4; nb++) {
            int c = nb * 8 + 2 * tq;
            *reinterpret_cast<float2*>(o0 + c) = make_float2(acc[mi][nb][0], acc[mi][nb][1]);
            *reinterpret_cast<float2*>(o1 + c) = make_float2(acc[mi][nb][2], acc[mi][nb][3]);
        }
    }
}

extern "C" void kernel_launch(void* const* d_in, const int* in_sizes, int n_in,
                              void* d_out, int out_size) {
    const float* x       = (const float*)d_in[0];
    const int*   qweight = (const int*)d_in[1];
    const float* scales  = (const float*)d_in[2];
    const int*   qzeros  = (const int*)d_in[3];
    float*       out     = (float*)d_out;

    static int configured = 0;
    if (!configured) {
        cudaFuncSetAttribute(q4_tf32_mma, cudaFuncAttributeMaxDynamicSharedMemorySize, SMEM_BYTES);
        configured = 1;
    }

    // 1) round x -> tf32 scratch (idempotent, graph-capturable)
    round_x_kernel<<<(I_DIM * 4096 / 4) / 256, 256>>>((const float4*)x);

    // 2) GEMM
    dim3 grid(O_DIM / BN, 4096 / BM);   // (43, 32)
    q4_tf32_mma<<<grid, THREADS, SMEM_BYTES>>>(qweight, scales, qzeros, out);
}

// round 7
// speedup vs baseline: 1.2589x; 1.2589x over previous
#include <cuda_runtime.h>
#include <cstdint>

// x:[4096,4096] f32, qweight:[4096,1376] i32 (8x int4 along O), scales:[32,11008] f32,
// qzeros:[32,1376] i32, out:[4096,11008] f32, group_size=128.
// tf32 mma.sync GEMM. Pre-kernel writes x (tf32-rounded) into per-tile SMEM-image
// layout; main kernel cp.async's images verbatim (identity copy, coalesced).

#define I_DIM 4096
#define O_DIM 11008
#define OPACK 1376
#define BM 128
#define BN 256
#define BK 32
#define NITER 128
#define THREADS 256

#define A_WORDS (BM * BK)                 // 4096 words = 16KB per stage image
#define B_WORDS (BN * BK)                 // 8192
#define STAGE_WORDS (A_WORDS + B_WORDS)   // 12288
#define SMEM_BYTES (2 * STAGE_WORDS * 4)  // 98304

// scratch: x pre-rounded to tf32, tiled as [rt(32)][kt(128)][4096 words] SMEM images
__device__ uint32_t g_xr[(size_t)32 * 128 * A_WORDS];

__device__ __forceinline__ uint32_t f2tf32(float f) {
    uint32_t u;
    asm("cvt.rna.tf32.f32 %0, %1;" : "=r"(u) : "f"(f));
    return u;
}

__device__ __forceinline__ uint32_t smem_u32(const void* p) {
    uint32_t a;
    asm("{ .reg .u64 t; cvta.to.shared.u64 t, %1; cvt.u32.u64 %0, t; }" : "=r"(a) : "l"(p));
    return a;
}

__device__ __forceinline__ void cp_async16(uint32_t dst, const void* src) {
    asm volatile("cp.async.cg.shared.global [%0], [%1], 16;" :: "r"(dst), "l"(src) : "memory");
}

__device__ __forceinline__ void mma_tf32(float* d, const uint32_t* a, const uint32_t* b) {
    asm volatile(
        "mma.sync.aligned.m16n8k8.row.col.f32.tf32.tf32.f32 "
        "{%0,%1,%2,%3},{%4,%5,%6,%7},{%8,%9},{%0,%1,%2,%3};"
        : "+f"(d[0]), "+f"(d[1]), "+f"(d[2]), "+f"(d[3])
        : "r"(a[0]), "r"(a[1]), "r"(a[2]), "r"(a[3]), "r"(b[0]), "r"(b[1]));
}

// ---- pre-kernel: round x to tf32 and lay out as per-tile SMEM images ----
// A-image word(r,k) = r*32 + ((k>>2 ^ (r&7))<<2) + (k&3)   [identical to R4 smem layout]
__global__ __launch_bounds__(256)
void round_x_kernel(const float4* __restrict__ x) {
    size_t idx = (size_t)blockIdx.x * 256 + threadIdx.x;   // over float4 chunks
    int r  = (int)(idx >> 10);        // global row
    int c4 = (int)(idx & 1023);       // 16B chunk within row
    float4 v = x[idx];
    uint4 u;
    u.x = f2tf32(v.x); u.y = f2tf32(v.y); u.z = f2tf32(v.z); u.w = f2tf32(v.w);
    int rt = r >> 7, rl = r & 127;
    int kt = c4 >> 3, af4 = c4 & 7;
    uint32_t p = rl * 32 + ((af4 ^ (rl & 7)) << 2);
    *reinterpret_cast<uint4*>(g_xr + (((size_t)rt * 128 + kt) << 12) + p) = u;
}

// ---- main GEMM ----
__global__ __launch_bounds__(THREADS, 1)
void q4_tf32_mma(const int* __restrict__ qweight,
                 const float* __restrict__ scales,
                 const int* __restrict__ qzeros,
                 float* __restrict__ out) {
    extern __shared__ uint32_t smem[];
    const uint32_t sbase = smem_u32(smem);

    const int tid  = threadIdx.x;
    const int lane = tid & 31;
    const int wid  = tid >> 5;
    const int gi   = lane >> 2;
    const int tq   = lane & 3;

    const int row0 = blockIdx.y * BM;
    const int col0 = blockIdx.x * BN;

    // 8 warps: 2 (M, tile 64) x 4 (N, tile 64)
    const int wm = wid & 1;
    const int wn = wid >> 1;

    const int ow = tid & 31;
    const int kt = tid >> 5;   // 0..7 -> k quad base 4*kt
    const int*   qw_base = qweight + (col0 >> 3) + ow;
    const int*   qz_base = qzeros  + (col0 >> 3) + ow;
    const float* sc_base = scales  + col0 + ow * 8;

    const uint32_t* a_img = g_xr + (((size_t)(row0 >> 7)) * 128 << 12);

    uint32_t wS[4];
    uint32_t zS;
    float4 sS0, sS1;

    float acc[4][8][4];
#pragma unroll
    for (int mi = 0; mi < 4; mi++)
#pragma unroll
        for (int nb = 0; nb < 8; nb++)
#pragma unroll
            for (int j = 0; j < 4; j++) acc[mi][nb][j] = 0.0f;

    // A: identity cp.async of the pre-built 16KB image
    auto issueA = [&](int it, int stage) {
        const uint32_t aB = sbase + stage * (STAGE_WORDS * 4);
        const uint32_t* src = a_img + ((size_t)it << 12);
#pragma unroll
        for (int j = 0; j < 4; j++) {
            int c = tid + j * 256;                  // 0..1023 16B chunks
            cp_async16(aB + c * 16, src + c * 4);
        }
        asm volatile("cp.async.commit_group;" ::: "memory");
    };

    auto loadB = [&](int it) {
        const int k0 = it * BK;
#pragma unroll
        for (int j = 0; j < 4; j++)
            wS[j] = (uint32_t)qw_base[(size_t)(k0 + kt * 4 + j) * OPACK];
        const int g = it >> 2;
        zS  = (uint32_t)qz_base[(size_t)g * OPACK];
        sS0 = *reinterpret_cast<const float4*>(sc_base + (size_t)g * O_DIM);
        sS1 = *reinterpret_cast<const float4*>(sc_base + (size_t)g * O_DIM + 4);
    };

    // B: word(n,k) = n*32 + ((k>>2 ^ (n&7) ^ ((n>>3)&7))<<2) + (k&3)
    auto storeB = [&](int stage) {
        uint32_t* Bs = smem + stage * STAGE_WORDS + A_WORDS;
        float sc[8] = {sS0.x, sS0.y, sS0.z, sS0.w, sS1.x, sS1.y, sS1.z, sS1.w};
#pragma unroll
        for (int o = 0; o < 8; o++) {
            float fz = __uint_as_float(0x4B000000u | ((zS >> (4 * o)) & 0xF));
            uint4 v;
            float f;
            f = __uint_as_float(0x4B000000u | ((wS[0] >> (4 * o)) & 0xF)); v.x = f2tf32((f - fz) * sc[o]);
            f = __uint_as_float(0x4B000000u | ((wS[1] >> (4 * o)) & 0xF)); v.y = f2tf32((f - fz) * sc[o]);
            f = __uint_as_float(0x4B000000u | ((wS[2] >> (4 * o)) & 0xF)); v.z = f2tf32((f - fz) * sc[o]);
            f = __uint_as_float(0x4B000000u | ((wS[3] >> (4 * o)) & 0xF)); v.w = f2tf32((f - fz) * sc[o]);
            int n = ow * 8 + o;
            uint32_t w = n * 32 + ((kt ^ (o ^ (ow & 7))) << 2);
            *reinterpret_cast<uint4*>(Bs + w) = v;
        }
    };

    auto compute = [&](int stage) {
        const uint32_t* As = smem + stage * STAGE_WORDS;
        const uint32_t* Bs = As + A_WORDS;
#pragma unroll
        for (int kb = 0; kb < 4; kb++) {
            uint32_t a[4][4];
#pragma unroll
            for (int mi = 0; mi < 4; mi++) {
                uint32_t base = (wm * 64 + mi * 16 + gi) * 32 + (((2 * kb) ^ gi) << 2) + tq;
                a[mi][0] = As[base];
                a[mi][1] = As[base + 256];
                a[mi][2] = As[base ^ 4];
                a[mi][3] = As[(base ^ 4) + 256];
            }
            uint32_t b[8][2];
#pragma unroll
            for (int nb = 0; nb < 8; nb++) {
                uint32_t base = (wn * 64 + nb * 8 + gi) * 32 + (((2 * kb) ^ (gi ^ nb)) << 2) + tq;
                b[nb][0] = Bs[base];
                b[nb][1] = Bs[base ^ 4];
            }
#pragma unroll
            for (int mi = 0; mi < 4; mi++)
#pragma unroll
                for (int nb = 0; nb < 8; nb++)
                    mma_tf32(acc[mi][nb], a[mi], b[nb]);
        }
    };

    // ---------------- pipeline ----------------
    issueA(0, 0);
    loadB(0);
    asm volatile("cp.async.wait_group 0;" ::: "memory");
    storeB(0);
    __syncthreads();

    for (int it = 0; it < NITER; ++it) {
        const int s = it & 1;
        if (it + 1 < NITER) {
            issueA(it + 1, s ^ 1);
            loadB(it + 1);
        }
        compute(s);
        if (it + 1 < NITER) {
            asm volatile("cp.async.wait_group 0;" ::: "memory");
            storeB(s ^ 1);
        }
        __syncthreads();
    }

    // ---------------- epilogue ----------------
#pragma unroll
    for (int mi = 0; mi < 4; mi++) {
        int r = row0 + wm * 64 + mi * 16 + gi;
        float* o0 = out + (size_t)r * O_DIM + col0 + wn * 64;
        float* o1 = o0 + 8 * O_DIM;
#pragma unroll
        for (int nb = 0; nb < 8; nb++) {
            int c = nb * 8 + 2 * tq;
            *reinterpret_cast<float2*>(o0 + c) = make_float2(acc[mi][nb][0], acc[mi][nb][1]);
            *reinterpret_cast<float2*>(o1 + c) = make_float2(acc[mi][nb][2], acc[mi][nb][3]);
        }
    }
}

extern "C" void kernel_launch(void* const* d_in, const int* in_sizes, int n_in,
                              void* d_out, int out_size) {
    const float* x       = (const float*)d_in[0];
    const int*   qweight = (const int*)d_in[1];
    const float* scales  = (const float*)d_in[2];
    const int*   qzeros  = (const int*)d_in[3];
    float*       out     = (float*)d_out;

    static int configured = 0;
    if (!configured) {
        cudaFuncSetAttribute(q4_tf32_mma, cudaFuncAttributeMaxDynamicSharedMemorySize, SMEM_BYTES);
        configured = 1;
    }

    // 1) round + re-layout x into tiled tf32 images (idempotent, capturable)
    round_x_kernel<<<(4096 * 1024) / 256, 256>>>((const float4*)x);

    // 2) GEMM
    dim3 grid(O_DIM / BN, 4096 / BM);   // (43, 32)
    q4_tf32_mma<<<grid, THREADS, SMEM_BYTES>>>(qweight, scales, qzeros, out);
}